// round 14
// baseline (speedup 1.0000x reference)
#include <cuda_runtime.h>
#include <cuda_bf16.h>
#include <cooperative_groups.h>
#include <cstdint>
#include <math.h>

namespace cg = cooperative_groups;

#define IN_DIM 128
#define HID    32
#define NCLS   30
#define CP     32            // padded row width (128B fp32 rows)
#define NMAX   100000
#define EMAX   3200000
#define EPAD   4001024       // >= EMAX + 8*(NMAX+1)
#define G2MAX  2048          // gather2 grid size (fixed)
#define PARTM  32768
#define REG_C  0.01

// ---------------- static scratch (zero-initialized at load) ----------------
__device__ float  d_g1 [(NMAX + 1) * CP];   // g1 rows + zero sentinel row N
__device__ float  d_g2 [(NMAX + 1) * CP];   // g2 rows + zero sentinel row N
__device__ __nv_bfloat162 d_fx16[NMAX * 16];
__device__ int    d_cnt [NMAX + 1];         // zeroed by ff_k tail each replay
__device__ int    d_cur [NMAX + 1];
__device__ int    d_rp  [NMAX + 1];         // padded CSR row pointers (mult of 8)
__device__ int    d_src32[EMAX];
__device__ int    d_dst32[EMAX];
__device__ int    d_csr [EPAD];
__device__ float  d_dinv[NMAX + 1];
__device__ int    d_blocksum[1024];
__device__ float  d_partialS[32 * G2MAX];
__device__ float  d_partialM[PARTM];
__device__ int    d_is64;

// ==== kernel 1 (cooperative): dtype detect + convert/count + gemm1 raw =====
__global__ void __launch_bounds__(256) k_count_gemm(
    const float* __restrict__ x, const float* __restrict__ W1,
    const void* __restrict__ ei, int E, int N)
{
    cg::grid_group grid = cg::this_grid();

    // dtype detect (block 0, warps 0-1)
    if (blockIdx.x == 0 && threadIdx.x < 64) {
        const unsigned int* w = (const unsigned int*)ei;
        unsigned int v = w[2 * threadIdx.x + 1];       // hi-words if int64
        unsigned int any = __ballot_sync(0xffffffffu, v != 0);
        if (threadIdx.x == 0) d_is64 = (any == 0) ? 1 : 0;
    }
    grid.sync();

    int is64 = d_is64;
    int nthreads = gridDim.x * blockDim.x;
    int tid = blockIdx.x * blockDim.x + threadIdx.x;

    // edge convert + in-degree count
    for (int e = tid; e < E; e += nthreads) {
        int s, d;
        if (is64) {
            const long long* p = (const long long*)ei;
            s = (int)p[e]; d = (int)p[(size_t)E + e];
        } else {
            const int* p = (const int*)ei;
            s = p[e]; d = p[(size_t)E + e];
        }
        d_src32[e] = s; d_dst32[e] = d;
        atomicAdd(&d_cnt[d], 1);
    }

    // gemm1 raw: g1 = x @ W1
    __shared__ float Ws[IN_DIM * HID];
    for (int i = threadIdx.x; i < IN_DIM * HID; i += blockDim.x) Ws[i] = W1[i];
    __syncthreads();

    for (int r = tid; r < N; r += nthreads) {
        float acc[HID];
#pragma unroll
        for (int c = 0; c < HID; c++) acc[c] = 0.f;
        const float4* x4 = reinterpret_cast<const float4*>(x + (size_t)r * IN_DIM);
#pragma unroll 4
        for (int k4 = 0; k4 < IN_DIM / 4; k4++) {
            float4 xv = x4[k4];
            int k = k4 * 4;
#pragma unroll
            for (int c = 0; c < HID; c++) {
                acc[c] += xv.x * Ws[(k + 0) * HID + c]
                        + xv.y * Ws[(k + 1) * HID + c]
                        + xv.z * Ws[(k + 2) * HID + c]
                        + xv.w * Ws[(k + 3) * HID + c];
            }
        }
        float* out = d_g1 + (size_t)r * CP;
#pragma unroll
        for (int c = 0; c < HID; c++) out[c] = acc[c];
    }
}

// ==== kernel 2 (cooperative): dinv + padded scan + rp/sentinels + scale + fill
__global__ void __launch_bounds__(1024) k_scan_fill(int N, int E) {
    cg::grid_group grid = cg::this_grid();
    __shared__ int sh[1024];
    __shared__ int off_sh;

    int gid = blockIdx.x * 1024 + threadIdx.x;
    int cnt = 0, v = 0;
    if (gid <= N) { cnt = d_cnt[gid]; v = (cnt + 7) & ~7; }   // padded degree
    if (gid < N)  d_dinv[gid] = rsqrtf((float)(cnt + 1));     // +1 self loop
    if (gid == N) d_dinv[N] = 0.f;                            // sentinel

    sh[threadIdx.x] = v; __syncthreads();
    for (int off = 1; off < 1024; off <<= 1) {
        int t = (threadIdx.x >= off) ? sh[threadIdx.x - off] : 0;
        __syncthreads();
        sh[threadIdx.x] += t;
        __syncthreads();
    }
    int incl = sh[threadIdx.x];
    if (threadIdx.x == 1023) d_blocksum[blockIdx.x] = incl;

    grid.sync();

    // per-block offset = sum of previous block sums
    int lane = threadIdx.x & 31;
    if (threadIdx.x < 32) {
        int s = 0;
        for (int k = lane; k < blockIdx.x; k += 32) s += d_blocksum[k];
#pragma unroll
        for (int o = 16; o; o >>= 1) s += __shfl_down_sync(0xffffffffu, s, o);
        if (lane == 0) off_sh = s;
    }
    __syncthreads();

    if (gid <= N) {
        int rp = (incl - v) + off_sh;
        d_rp[gid] = rp;
        d_cur[gid] = rp;                           // fill cursor
        if (gid < N) {
            int end = rp + ((cnt + 7) & ~7);
            for (int p = rp + cnt; p < end; p++) d_csr[p] = N;   // sentinel tail
        }
    }

    grid.sync();

    int nthreads = gridDim.x * blockDim.x;
    int tid = gid;

    // scale g1 rows by dinv
    int n4 = N * CP / 4;
    for (int i = tid; i < n4; i += nthreads) {
        float s = d_dinv[i >> 3];
        float4* p = reinterpret_cast<float4*>(d_g1) + i;
        float4 val = *p;
        val.x *= s; val.y *= s; val.z *= s; val.w *= s;
        *p = val;
    }

    // CSR fill
    for (int e = tid; e < E; e += nthreads) {
        int d = d_dst32[e];
        int pos = atomicAdd(&d_cur[d], 1);
        d_csr[pos] = d_src32[e];
    }
}

// ---- gather layer1 (float4 quads: 8 edges / 2 LDG.128) + fused GEMM2 ------
__global__ void __launch_bounds__(256) gather1(const float* __restrict__ b1,
                                               const float* __restrict__ W2, int N) {
    __shared__ float Ws[HID * CP];
    for (int i = threadIdx.x; i < HID * CP; i += blockDim.x) {
        int k = i / CP, c = i % CP;
        Ws[i] = (c < NCLS) ? W2[k * NCLS + c] : 0.f;
    }
    __syncthreads();

    int tid  = threadIdx.x;
    int lane = tid & 31;
    int q    = lane & 7;          // feature quad 0..7
    int eg   = lane >> 3;         // edge group 0..3
    int warp = (blockIdx.x * blockDim.x + tid) >> 5;
    int nwarps = (gridDim.x * blockDim.x) >> 5;
    float4 bv4 = reinterpret_cast<const float4*>(b1)[q];

    for (int v = warp; v < N; v += nwarps) {
        int beg = d_rp[v];
        int nb  = (d_rp[v + 1] - beg) >> 3;          // blocks of 8 edges
        const int4* ip = reinterpret_cast<const int4*>(d_csr + beg);
        float4 acc = make_float4(0.f, 0.f, 0.f, 0.f);
        int4 ia, ib;
        if (nb > 0) { ia = ip[0]; ib = ip[1]; }
        for (int b = 0; b < nb; b++) {
            int4 na, nbx;
            if (b + 1 < nb) { na = ip[2 * b + 2]; nbx = ip[2 * b + 3]; }
            int s0 = (eg == 0) ? ia.x : (eg == 1) ? ia.y : (eg == 2) ? ia.z : ia.w;
            int s1 = (eg == 0) ? ib.x : (eg == 1) ? ib.y : (eg == 2) ? ib.z : ib.w;
            float4 va = *reinterpret_cast<const float4*>(d_g1 + (size_t)s0 * CP + q * 4);
            float4 vb = *reinterpret_cast<const float4*>(d_g1 + (size_t)s1 * CP + q * 4);
            acc.x += va.x + vb.x; acc.y += va.y + vb.y;
            acc.z += va.z + vb.z; acc.w += va.w + vb.w;
            ia = na; ib = nbx;
        }
        // reduce across the 4 edge groups (lanes xor 8, 16)
#pragma unroll
        for (int o = 8; o <= 16; o <<= 1) {
            acc.x += __shfl_xor_sync(0xffffffffu, acc.x, o);
            acc.y += __shfl_xor_sync(0xffffffffu, acc.y, o);
            acc.z += __shfl_xor_sync(0xffffffffu, acc.z, o);
            acc.w += __shfl_xor_sync(0xffffffffu, acc.w, o);
        }
        float4 self = *reinterpret_cast<const float4*>(d_g1 + (size_t)v * CP + q * 4);
        float dv = d_dinv[v];
        float4 h;
        h.x = fmaxf(dv * (acc.x + self.x) + bv4.x, 0.f);
        h.y = fmaxf(dv * (acc.y + self.y) + bv4.y, 0.f);
        h.z = fmaxf(dv * (acc.z + self.z) + bv4.z, 0.f);
        h.w = fmaxf(dv * (acc.w + self.w) + bv4.w, 0.f);

        // fused GEMM2: g2[c] = dv * sum_k h[k] * W2[k][c], c = lane
        float g2c = 0.f;
#pragma unroll
        for (int q2 = 0; q2 < 8; q2++) {
            float hx = __shfl_sync(0xffffffffu, h.x, q2);
            float hy = __shfl_sync(0xffffffffu, h.y, q2);
            float hz = __shfl_sync(0xffffffffu, h.z, q2);
            float hw = __shfl_sync(0xffffffffu, h.w, q2);
            g2c += hx * Ws[(4 * q2 + 0) * CP + lane] + hy * Ws[(4 * q2 + 1) * CP + lane]
                 + hz * Ws[(4 * q2 + 2) * CP + lane] + hw * Ws[(4 * q2 + 3) * CP + lane];
        }
        d_g2[(size_t)v * CP + lane] = dv * g2c;
    }
}

// ---- gather layer2 (float4 quads) + softmax + FX + bf16 copy + NFX --------
__global__ void __launch_bounds__(256) gather2(const float* __restrict__ b2,
                                               float* __restrict__ fx_out, int N) {
    __shared__ float Ss[32];
    __shared__ float b2s[32];
    int tid  = threadIdx.x;
    int lane = tid & 31;
    if (tid < 32) { Ss[tid] = 0.f; b2s[tid] = (tid < NCLS) ? b2[tid] : 0.f; }
    __syncthreads();

    int q    = lane & 7;
    int eg   = lane >> 3;
    int warp = (blockIdx.x * blockDim.x + tid) >> 5;
    int nwarps = (gridDim.x * blockDim.x) >> 5;
    float4 bv4 = reinterpret_cast<const float4*>(b2s)[q];
    float4 ls4 = make_float4(0.f, 0.f, 0.f, 0.f);

    for (int v = warp; v < N; v += nwarps) {
        int beg = d_rp[v];
        int nb  = (d_rp[v + 1] - beg) >> 3;
        const int4* ip = reinterpret_cast<const int4*>(d_csr + beg);
        float4 acc = make_float4(0.f, 0.f, 0.f, 0.f);
        int4 ia, ib;
        if (nb > 0) { ia = ip[0]; ib = ip[1]; }
        for (int b = 0; b < nb; b++) {
            int4 na, nbx;
            if (b + 1 < nb) { na = ip[2 * b + 2]; nbx = ip[2 * b + 3]; }
            int s0 = (eg == 0) ? ia.x : (eg == 1) ? ia.y : (eg == 2) ? ia.z : ia.w;
            int s1 = (eg == 0) ? ib.x : (eg == 1) ? ib.y : (eg == 2) ? ib.z : ib.w;
            float4 va = *reinterpret_cast<const float4*>(d_g2 + (size_t)s0 * CP + q * 4);
            float4 vb = *reinterpret_cast<const float4*>(d_g2 + (size_t)s1 * CP + q * 4);
            acc.x += va.x + vb.x; acc.y += va.y + vb.y;
            acc.z += va.z + vb.z; acc.w += va.w + vb.w;
            ia = na; ib = nbx;
        }
#pragma unroll
        for (int o = 8; o <= 16; o <<= 1) {
            acc.x += __shfl_xor_sync(0xffffffffu, acc.x, o);
            acc.y += __shfl_xor_sync(0xffffffffu, acc.y, o);
            acc.z += __shfl_xor_sync(0xffffffffu, acc.z, o);
            acc.w += __shfl_xor_sync(0xffffffffu, acc.w, o);
        }
        float4 self = *reinterpret_cast<const float4*>(d_g2 + (size_t)v * CP + q * 4);
        float dv = d_dinv[v];
        float4 lg;
        lg.x = dv * (acc.x + self.x) + bv4.x;
        lg.y = dv * (acc.y + self.y) + bv4.y;
        lg.z = dv * (acc.z + self.z) + bv4.z;
        lg.w = dv * (acc.w + self.w) + bv4.w;
        if (q == 7) { lg.z = -1e30f; lg.w = -1e30f; }   // classes 30,31

        float mx = fmaxf(fmaxf(lg.x, lg.y), fmaxf(lg.z, lg.w));
#pragma unroll
        for (int o = 1; o <= 4; o <<= 1) mx = fmaxf(mx, __shfl_xor_sync(0xffffffffu, mx, o));
        float4 ex;
        ex.x = expf(lg.x - mx); ex.y = expf(lg.y - mx);
        ex.z = expf(lg.z - mx); ex.w = expf(lg.w - mx);
        float sum = ex.x + ex.y + ex.z + ex.w;
#pragma unroll
        for (int o = 1; o <= 4; o <<= 1) sum += __shfl_xor_sync(0xffffffffu, sum, o);
        float inv = 1.f / sum;
        float4 fx;
        fx.x = ex.x * inv; fx.y = ex.y * inv; fx.z = ex.z * inv; fx.w = ex.w * inv;

        if (eg == 0) {
            float* base = fx_out + (size_t)v * NCLS;
            *reinterpret_cast<float2*>(base + 4 * q) = make_float2(fx.x, fx.y);
            if (q < 7)
                *reinterpret_cast<float2*>(base + 4 * q + 2) = make_float2(fx.z, fx.w);
            __nv_bfloat162 p0 = __floats2bfloat162_rn(fx.x, fx.y);
            __nv_bfloat162 p1 = __floats2bfloat162_rn(fx.z, fx.w);
            d_fx16[(size_t)v * 16 + 2 * q]     = p0;
            d_fx16[(size_t)v * 16 + 2 * q + 1] = p1;
        }
        ls4.x += log1pf(-fx.x * fx.x);
        ls4.y += log1pf(-fx.y * fx.y);
        ls4.z += log1pf(-fx.z * fx.z);
        ls4.w += log1pf(-fx.w * fx.w);
    }
    if (eg == 0) {
        atomicAdd(&Ss[4 * q + 0], ls4.x);
        atomicAdd(&Ss[4 * q + 1], ls4.y);
        atomicAdd(&Ss[4 * q + 2], ls4.z);
        atomicAdd(&Ss[4 * q + 3], ls4.w);
    }
    __syncthreads();
    if (tid < NCLS) d_partialS[tid * gridDim.x + blockIdx.x] = Ss[tid];
}

// ---------------- FF + MSE partials + d_cnt re-zero for next replay --------
__global__ void ff_k(const float* __restrict__ ep, int E, int N) {
    __shared__ float sAcc;
    int tid = threadIdx.x;
    if (tid == 0) sAcc = 0.f;
    __syncthreads();

    int idx = blockIdx.x * blockDim.x + tid;

    // re-zero d_cnt for the next replay (all consumers ran earlier this replay)
    int nthreads = gridDim.x * blockDim.x;
    for (int i = idx; i <= N; i += nthreads) d_cnt[i] = 0;

    int grp = idx >> 2, c = idx & 3;
    int e0 = grp * 2;
    int nGrp = (E + 1) >> 1;
    bool v0 = (grp < nGrp) && (e0 < E);
    bool v1 = (grp < nGrp) && (e0 + 1 < E);

    float p0 = 0.f, p1 = 0.f;
    if (v0) {
        int s0 = d_src32[e0], dd0 = d_dst32[e0];
        uint4 A0 = reinterpret_cast<const uint4*>(d_fx16 + (size_t)s0  * 16)[c];
        uint4 B0 = reinterpret_cast<const uint4*>(d_fx16 + (size_t)dd0 * 16)[c];
        const unsigned int aw[4] = {A0.x, A0.y, A0.z, A0.w};
        const unsigned int bw[4] = {B0.x, B0.y, B0.z, B0.w};
#pragma unroll
        for (int j = 0; j < 4; j++) {
            float2 af = __bfloat1622float2(*reinterpret_cast<const __nv_bfloat162*>(&aw[j]));
            float2 bf = __bfloat1622float2(*reinterpret_cast<const __nv_bfloat162*>(&bw[j]));
            p0 += af.x * bf.x + af.y * bf.y;
        }
    }
    if (v1) {
        int s1 = d_src32[e0 + 1], dd1 = d_dst32[e0 + 1];
        uint4 A1 = reinterpret_cast<const uint4*>(d_fx16 + (size_t)s1  * 16)[c];
        uint4 B1 = reinterpret_cast<const uint4*>(d_fx16 + (size_t)dd1 * 16)[c];
        const unsigned int aw[4] = {A1.x, A1.y, A1.z, A1.w};
        const unsigned int bw[4] = {B1.x, B1.y, B1.z, B1.w};
#pragma unroll
        for (int j = 0; j < 4; j++) {
            float2 af = __bfloat1622float2(*reinterpret_cast<const __nv_bfloat162*>(&aw[j]));
            float2 bf = __bfloat1622float2(*reinterpret_cast<const __nv_bfloat162*>(&bw[j]));
            p1 += af.x * bf.x + af.y * bf.y;
        }
    }

    p0 += __shfl_down_sync(0xffffffffu, p0, 1);
    p0 += __shfl_down_sync(0xffffffffu, p0, 2);
    p1 += __shfl_down_sync(0xffffffffu, p1, 1);
    p1 += __shfl_down_sync(0xffffffffu, p1, 2);

    float d2 = 0.f;
    if (c == 0) {
        if (v0) { float f = p0 - ep[e0];     d2 += f * f; }
        if (v1) { float f = p1 - ep[e0 + 1]; d2 += f * f; }
    }
    d2 += __shfl_down_sync(0xffffffffu, d2, 4);
    d2 += __shfl_down_sync(0xffffffffu, d2, 8);
    d2 += __shfl_down_sync(0xffffffffu, d2, 16);
    if ((tid & 31) == 0) atomicAdd(&sAcc, d2);
    __syncthreads();
    if (tid == 0) d_partialM[blockIdx.x] = sAcc;
}

// ---------------- finalize loss -------------------------------------------
__global__ void fin_k(float* __restrict__ out, int N, int E, int out_size, int nb_m) {
    __shared__ double sS[32];
    __shared__ double red[32];
    int tid = threadIdx.x, w = tid >> 5, lane = tid & 31;

    if (w < NCLS) {
        float s = 0.f;
        for (int k = lane; k < G2MAX; k += 32) s += d_partialS[w * G2MAX + k];
#pragma unroll
        for (int o = 16; o; o >>= 1) s += __shfl_down_sync(0xffffffffu, s, o);
        if (lane == 0) sS[w] = (double)s;
    }

    double m = 0.0;
    for (int k = tid; k < nb_m; k += 1024) m += (double)d_partialM[k];
#pragma unroll
    for (int o = 16; o; o >>= 1) m += __shfl_down_sync(0xffffffffu, m, o);
    if (lane == 0) red[w] = m;
    __syncthreads();

    if (tid == 0) {
        double mm = 0.0;
        for (int i = 0; i < 32; i++) mm += red[i];
        double preg = 0.0;
        for (int c = 0; c < NCLS; c++)
            preg -= log(1.0001 - exp(sS[c]));
        double loss = mm / (double)E + REG_C * preg;
        if (out_size > N * NCLS) out[(size_t)N * NCLS] = (float)loss;
    }
}

// ---------------- launch ---------------------------------------------------
extern "C" void kernel_launch(void* const* d_in, const int* in_sizes, int n_in,
                              void* d_out, int out_size) {
    const float* x   = (const float*)d_in[0];
    const void*  ei  = d_in[1];
    const float* ep  = (const float*)d_in[2];
    const float* W1  = (const float*)d_in[3];
    const float* b1  = (const float*)d_in[4];
    const float* W2  = (const float*)d_in[5];
    const float* b2  = (const float*)d_in[6];
    float* out = (float*)d_out;

    int N = in_sizes[0] / IN_DIM;    // 100000
    int E = in_sizes[2];             // 3200000
    int nb_scan = (N + 1 + 1023) / 1024;          // 98 blocks, co-resident
    long long ff_threads = ((long long)E + 1) / 2 * 4;
    int nb_ff   = (int)((ff_threads + 1023) / 1024);

    // 1) cooperative: detect + convert/count + gemm1 raw  (296 blocks, 2/SM safe)
    {
        void* args[] = {(void*)&x, (void*)&W1, (void*)&ei, (void*)&E, (void*)&N};
        cudaLaunchCooperativeKernel((void*)k_count_gemm, dim3(296), dim3(256), args, 0, 0);
    }
    // 2) cooperative: dinv + padded scan + rp/sentinels + g1 scale + fill
    {
        void* args[] = {(void*)&N, (void*)&E};
        cudaLaunchCooperativeKernel((void*)k_scan_fill, dim3(nb_scan), dim3(1024), args, 0, 0);
    }
    // 3-6) the fused pipeline (launch 4 = gather2 -> ncu slot)
    gather1<<<2048, 256>>>(b1, W2, N);
    gather2<<<G2MAX, 256>>>(b2, out, N);
    ff_k   <<<nb_ff, 1024>>>(ep, E, N);
    fin_k  <<<1, 1024>>>(out, N, E, out_size, nb_ff);
}

// round 15
// speedup vs baseline: 1.1995x; 1.1995x over previous
#include <cuda_runtime.h>
#include <cuda_bf16.h>
#include <cstdint>
#include <math.h>

#define IN_DIM 128
#define HID    32
#define NCLS   30
#define CP     32            // padded row width (128B fp32 rows)
#define NMAX   100000
#define EMAX   3200000
#define EPAD   4001024       // >= EMAX + 8*(NMAX+1) + 8
#define G2MAX  2048          // gather2 grid size (fixed)
#define PARTM  32768
#define REG_C  0.01

// ---------------- static scratch ----------------
__device__ float  d_g1 [(NMAX + 1) * CP];   // g1 rows + zero sentinel row N
__device__ float  d_g2 [(NMAX + 1) * CP];   // g2 rows + zero sentinel row N
__device__ __nv_bfloat162 d_fx16[NMAX * 16];
__device__ int    d_cnt [NMAX + 1];
__device__ int    d_cur [NMAX + 1];
__device__ int    d_rp  [NMAX + 1];         // padded CSR row pointers (mult of 8)
__device__ int    d_src32[EMAX];
__device__ int    d_dst32[EMAX];
__device__ int    d_csr [EPAD];
__device__ float  d_dinv[NMAX];
__device__ int    d_blocksum[1024];
__device__ float  d_partialS[32 * G2MAX];
__device__ float  d_partialM[PARTM];
__device__ int    d_is64;

// ---------------- init: cnt=0, zero sentinel rows, dtype detect ------------
__global__ void init_k(const unsigned int* __restrict__ w, int N) {
    int i = blockIdx.x * blockDim.x + threadIdx.x;
    if (i <= N) d_cnt[i] = 0;
    if (i < CP) {
        d_g1[(size_t)N * CP + i] = 0.f;
        d_g2[(size_t)N * CP + i] = 0.f;
    }
    if (blockIdx.x == 0 && threadIdx.x < 64) {
        unsigned int v = w[2 * threadIdx.x + 1];
        unsigned int any = __ballot_sync(0xffffffffu, v != 0);
        if (threadIdx.x == 0) d_is64 = (any == 0) ? 1 : 0;
    }
}

// ---------------- count + int32 conversion --------------------------------
__global__ void count_convert(const void* __restrict__ ei, int E) {
    int e = blockIdx.x * blockDim.x + threadIdx.x;
    if (e >= E) return;
    int s, d;
    if (d_is64) {
        const long long* p = (const long long*)ei;
        s = (int)p[e]; d = (int)p[(size_t)E + e];
    } else {
        const int* p = (const int*)ei;
        s = p[e]; d = p[(size_t)E + e];
    }
    d_src32[e] = s; d_dst32[e] = d;
    atomicAdd(&d_cnt[d], 1);
}

// ---------------- scan over PADDED counts (N+1 elements) + fused dinv ------
__global__ void scan1(int N) {
    __shared__ int sh[1024];
    int gid = blockIdx.x * 1024 + threadIdx.x;
    int cnt = 0, v = 0;
    if (gid <= N) { cnt = d_cnt[gid]; v = (cnt + 7) & ~7; }
    if (gid < N) d_dinv[gid] = rsqrtf((float)(cnt + 1));    // +1 self loop
    sh[threadIdx.x] = v; __syncthreads();
    for (int off = 1; off < 1024; off <<= 1) {
        int t = (threadIdx.x >= off) ? sh[threadIdx.x - off] : 0;
        __syncthreads();
        sh[threadIdx.x] += t;
        __syncthreads();
    }
    int incl = sh[threadIdx.x];
    if (gid <= N) d_cur[gid] = incl - v;          // block-local exclusive
    if (threadIdx.x == 1023) d_blocksum[blockIdx.x] = incl;
}

// scan3: inlined block offsets + rp/cursor write + sentinel tail padding
__global__ void scan3(int N) {
    __shared__ int off_sh;
    int lane = threadIdx.x & 31;
    if (threadIdx.x < 32) {
        int s = 0;
        for (int k = lane; k < blockIdx.x; k += 32) s += d_blocksum[k];
#pragma unroll
        for (int o = 16; o; o >>= 1) s += __shfl_down_sync(0xffffffffu, s, o);
        if (lane == 0) off_sh = s;
    }
    __syncthreads();
    int gid = blockIdx.x * 1024 + threadIdx.x;
    if (gid <= N) {
        int rp = d_cur[gid] + off_sh;
        d_rp[gid] = rp;
        d_cur[gid] = rp;                           // fill cursor
        if (gid < N) {
            int c = d_cnt[gid];
            int end = rp + ((c + 7) & ~7);
            for (int p = rp + c; p < end; p++) d_csr[p] = N;   // sentinel tail
        } else {
            // global tail: 8 sentinels past rp[N] for unconditional prefetch
            for (int p = rp; p < rp + 8; p++) d_csr[p] = N;
        }
    }
}

// ---------------- CSR fill -------------------------------------------------
__global__ void fill_k(int E) {
    int e = blockIdx.x * blockDim.x + threadIdx.x;
    if (e >= E) return;
    int d = d_dst32[e];
    int pos = atomicAdd(&d_cur[d], 1);
    d_csr[pos] = d_src32[e];
}

// ---------------- GEMM1 (raw): g1 = x @ W1 (aux stream) --------------------
__global__ void gemm1_raw(const float* __restrict__ x, const float* __restrict__ W1, int N) {
    __shared__ float Ws[IN_DIM * HID];
    for (int i = threadIdx.x; i < IN_DIM * HID; i += blockDim.x) Ws[i] = W1[i];
    __syncthreads();
    int r = blockIdx.x * blockDim.x + threadIdx.x;
    if (r >= N) return;

    float acc[HID];
#pragma unroll
    for (int c = 0; c < HID; c++) acc[c] = 0.f;

    const float4* x4 = reinterpret_cast<const float4*>(x + (size_t)r * IN_DIM);
#pragma unroll 4
    for (int k4 = 0; k4 < IN_DIM / 4; k4++) {
        float4 xv = x4[k4];
        int k = k4 * 4;
#pragma unroll
        for (int c = 0; c < HID; c++) {
            acc[c] += xv.x * Ws[(k + 0) * HID + c]
                    + xv.y * Ws[(k + 1) * HID + c]
                    + xv.z * Ws[(k + 2) * HID + c]
                    + xv.w * Ws[(k + 3) * HID + c];
        }
    }
    float* out = d_g1 + (size_t)r * CP;
#pragma unroll
    for (int c = 0; c < HID; c++) out[c] = acc[c];
}

// ---------------- scale g1 by dinv (join point) ----------------------------
__global__ void scaleg1(int N) {
    int i = blockIdx.x * blockDim.x + threadIdx.x;
    int n4 = N * CP / 4;
    if (i >= n4) return;
    float s = d_dinv[i >> 3];
    float4* p = reinterpret_cast<float4*>(d_g1) + i;
    float4 v = *p;
    v.x *= s; v.y *= s; v.z *= s; v.w *= s;
    *p = v;
}

// ---- gather layer1: scalar-pair indices, float4 rows, fused GEMM2 ---------
__global__ void __launch_bounds__(256) gather1(const float* __restrict__ b1,
                                               const float* __restrict__ W2, int N) {
    __shared__ float Ws[HID * CP];
    for (int i = threadIdx.x; i < HID * CP; i += blockDim.x) {
        int k = i / CP, c = i % CP;
        Ws[i] = (c < NCLS) ? W2[k * NCLS + c] : 0.f;
    }
    __syncthreads();

    int tid  = threadIdx.x;
    int lane = tid & 31;
    int q    = lane & 7;          // feature quad 0..7
    int eg   = lane >> 3;         // edge group 0..3
    int warp = (blockIdx.x * blockDim.x + tid) >> 5;
    int nwarps = (gridDim.x * blockDim.x) >> 5;
    float4 bv4 = reinterpret_cast<const float4*>(b1)[q];

    for (int v = warp; v < N; v += nwarps) {
        int beg = d_rp[v];
        int nb  = (d_rp[v + 1] - beg) >> 3;          // blocks of 8 edges
        const int2* ip = reinterpret_cast<const int2*>(d_csr + beg) + eg;
        float4 acc = make_float4(0.f, 0.f, 0.f, 0.f);
        int2 cur = ip[0];                            // safe: tail-padded
        for (int b = 0; b < nb; b++) {
            int2 nxt = ip[(b + 1) * 4];              // unconditional prefetch
            float4 va = *reinterpret_cast<const float4*>(d_g1 + (size_t)cur.x * CP + q * 4);
            float4 vb = *reinterpret_cast<const float4*>(d_g1 + (size_t)cur.y * CP + q * 4);
            acc.x += va.x + vb.x; acc.y += va.y + vb.y;
            acc.z += va.z + vb.z; acc.w += va.w + vb.w;
            cur = nxt;
        }
        // reduce across the 4 edge groups
#pragma unroll
        for (int o = 8; o <= 16; o <<= 1) {
            acc.x += __shfl_xor_sync(0xffffffffu, acc.x, o);
            acc.y += __shfl_xor_sync(0xffffffffu, acc.y, o);
            acc.z += __shfl_xor_sync(0xffffffffu, acc.z, o);
            acc.w += __shfl_xor_sync(0xffffffffu, acc.w, o);
        }
        float4 self = *reinterpret_cast<const float4*>(d_g1 + (size_t)v * CP + q * 4);
        float dv = d_dinv[v];
        float4 h;
        h.x = fmaxf(dv * (acc.x + self.x) + bv4.x, 0.f);
        h.y = fmaxf(dv * (acc.y + self.y) + bv4.y, 0.f);
        h.z = fmaxf(dv * (acc.z + self.z) + bv4.z, 0.f);
        h.w = fmaxf(dv * (acc.w + self.w) + bv4.w, 0.f);

        // fused GEMM2: g2[c] = dv * sum_k h[k] * W2[k][c], c = lane
        float g2c = 0.f;
#pragma unroll
        for (int q2 = 0; q2 < 8; q2++) {
            float hx = __shfl_sync(0xffffffffu, h.x, q2);
            float hy = __shfl_sync(0xffffffffu, h.y, q2);
            float hz = __shfl_sync(0xffffffffu, h.z, q2);
            float hw = __shfl_sync(0xffffffffu, h.w, q2);
            g2c += hx * Ws[(4 * q2 + 0) * CP + lane] + hy * Ws[(4 * q2 + 1) * CP + lane]
                 + hz * Ws[(4 * q2 + 2) * CP + lane] + hw * Ws[(4 * q2 + 3) * CP + lane];
        }
        d_g2[(size_t)v * CP + lane] = dv * g2c;
    }
}

// ---- gather layer2: scalar-pair indices + softmax + FX + bf16 + NFX -------
__global__ void __launch_bounds__(256) gather2(const float* __restrict__ b2,
                                               float* __restrict__ fx_out, int N) {
    __shared__ float Ss[32];
    __shared__ float b2s[32];
    int tid  = threadIdx.x;
    int lane = tid & 31;
    if (tid < 32) { Ss[tid] = 0.f; b2s[tid] = (tid < NCLS) ? b2[tid] : 0.f; }
    __syncthreads();

    int q    = lane & 7;
    int eg   = lane >> 3;
    int warp = (blockIdx.x * blockDim.x + tid) >> 5;
    int nwarps = (gridDim.x * blockDim.x) >> 5;
    float4 bv4 = reinterpret_cast<const float4*>(b2s)[q];
    float4 ls4 = make_float4(0.f, 0.f, 0.f, 0.f);

    for (int v = warp; v < N; v += nwarps) {
        int beg = d_rp[v];
        int nb  = (d_rp[v + 1] - beg) >> 3;
        const int2* ip = reinterpret_cast<const int2*>(d_csr + beg) + eg;
        float4 acc = make_float4(0.f, 0.f, 0.f, 0.f);
        int2 cur = ip[0];
        for (int b = 0; b < nb; b++) {
            int2 nxt = ip[(b + 1) * 4];
            float4 va = *reinterpret_cast<const float4*>(d_g2 + (size_t)cur.x * CP + q * 4);
            float4 vb = *reinterpret_cast<const float4*>(d_g2 + (size_t)cur.y * CP + q * 4);
            acc.x += va.x + vb.x; acc.y += va.y + vb.y;
            acc.z += va.z + vb.z; acc.w += va.w + vb.w;
            cur = nxt;
        }
#pragma unroll
        for (int o = 8; o <= 16; o <<= 1) {
            acc.x += __shfl_xor_sync(0xffffffffu, acc.x, o);
            acc.y += __shfl_xor_sync(0xffffffffu, acc.y, o);
            acc.z += __shfl_xor_sync(0xffffffffu, acc.z, o);
            acc.w += __shfl_xor_sync(0xffffffffu, acc.w, o);
        }
        float4 self = *reinterpret_cast<const float4*>(d_g2 + (size_t)v * CP + q * 4);
        float dv = d_dinv[v];
        float4 lg;
        lg.x = dv * (acc.x + self.x) + bv4.x;
        lg.y = dv * (acc.y + self.y) + bv4.y;
        lg.z = dv * (acc.z + self.z) + bv4.z;
        lg.w = dv * (acc.w + self.w) + bv4.w;
        if (q == 7) { lg.z = -1e30f; lg.w = -1e30f; }   // classes 30,31

        float mx = fmaxf(fmaxf(lg.x, lg.y), fmaxf(lg.z, lg.w));
#pragma unroll
        for (int o = 1; o <= 4; o <<= 1) mx = fmaxf(mx, __shfl_xor_sync(0xffffffffu, mx, o));
        float4 ex;
        ex.x = expf(lg.x - mx); ex.y = expf(lg.y - mx);
        ex.z = expf(lg.z - mx); ex.w = expf(lg.w - mx);
        float sum = ex.x + ex.y + ex.z + ex.w;
#pragma unroll
        for (int o = 1; o <= 4; o <<= 1) sum += __shfl_xor_sync(0xffffffffu, sum, o);
        float inv = 1.f / sum;
        float4 fx;
        fx.x = ex.x * inv; fx.y = ex.y * inv; fx.z = ex.z * inv; fx.w = ex.w * inv;

        if (eg == 0) {
            float* base = fx_out + (size_t)v * NCLS;
            *reinterpret_cast<float2*>(base + 4 * q) = make_float2(fx.x, fx.y);
            if (q < 7)
                *reinterpret_cast<float2*>(base + 4 * q + 2) = make_float2(fx.z, fx.w);
            __nv_bfloat162 p0 = __floats2bfloat162_rn(fx.x, fx.y);
            __nv_bfloat162 p1 = __floats2bfloat162_rn(fx.z, fx.w);
            d_fx16[(size_t)v * 16 + 2 * q]     = p0;
            d_fx16[(size_t)v * 16 + 2 * q + 1] = p1;
        }
        ls4.x += log1pf(-fx.x * fx.x);
        ls4.y += log1pf(-fx.y * fx.y);
        ls4.z += log1pf(-fx.z * fx.z);
        ls4.w += log1pf(-fx.w * fx.w);
    }
    if (eg == 0) {
        atomicAdd(&Ss[4 * q + 0], ls4.x);
        atomicAdd(&Ss[4 * q + 1], ls4.y);
        atomicAdd(&Ss[4 * q + 2], ls4.z);
        atomicAdd(&Ss[4 * q + 3], ls4.w);
    }
    __syncthreads();
    if (tid < NCLS) d_partialS[tid * gridDim.x + blockIdx.x] = Ss[tid];
}

// ---------------- FF + MSE partials (2 edges per 4-lane group) -------------
__global__ void ff_k(const float* __restrict__ ep, int E) {
    __shared__ float sAcc;
    int tid = threadIdx.x;
    if (tid == 0) sAcc = 0.f;
    __syncthreads();

    int idx = blockIdx.x * blockDim.x + tid;
    int grp = idx >> 2, c = idx & 3;
    int e0 = grp * 2;
    int nGrp = (E + 1) >> 1;
    bool v0 = (grp < nGrp) && (e0 < E);
    bool v1 = (grp < nGrp) && (e0 + 1 < E);

    float p0 = 0.f, p1 = 0.f;
    if (v0) {
        int s0 = d_src32[e0], dd0 = d_dst32[e0];
        uint4 A0 = reinterpret_cast<const uint4*>(d_fx16 + (size_t)s0  * 16)[c];
        uint4 B0 = reinterpret_cast<const uint4*>(d_fx16 + (size_t)dd0 * 16)[c];
        const unsigned int aw[4] = {A0.x, A0.y, A0.z, A0.w};
        const unsigned int bw[4] = {B0.x, B0.y, B0.z, B0.w};
#pragma unroll
        for (int j = 0; j < 4; j++) {
            float2 af = __bfloat1622float2(*reinterpret_cast<const __nv_bfloat162*>(&aw[j]));
            float2 bf = __bfloat1622float2(*reinterpret_cast<const __nv_bfloat162*>(&bw[j]));
            p0 += af.x * bf.x + af.y * bf.y;
        }
    }
    if (v1) {
        int s1 = d_src32[e0 + 1], dd1 = d_dst32[e0 + 1];
        uint4 A1 = reinterpret_cast<const uint4*>(d_fx16 + (size_t)s1  * 16)[c];
        uint4 B1 = reinterpret_cast<const uint4*>(d_fx16 + (size_t)dd1 * 16)[c];
        const unsigned int aw[4] = {A1.x, A1.y, A1.z, A1.w};
        const unsigned int bw[4] = {B1.x, B1.y, B1.z, B1.w};
#pragma unroll
        for (int j = 0; j < 4; j++) {
            float2 af = __bfloat1622float2(*reinterpret_cast<const __nv_bfloat162*>(&aw[j]));
            float2 bf = __bfloat1622float2(*reinterpret_cast<const __nv_bfloat162*>(&bw[j]));
            p1 += af.x * bf.x + af.y * bf.y;
        }
    }

    p0 += __shfl_down_sync(0xffffffffu, p0, 1);
    p0 += __shfl_down_sync(0xffffffffu, p0, 2);
    p1 += __shfl_down_sync(0xffffffffu, p1, 1);
    p1 += __shfl_down_sync(0xffffffffu, p1, 2);

    float d2 = 0.f;
    if (c == 0) {
        if (v0) { float f = p0 - ep[e0];     d2 += f * f; }
        if (v1) { float f = p1 - ep[e0 + 1]; d2 += f * f; }
    }
    d2 += __shfl_down_sync(0xffffffffu, d2, 4);
    d2 += __shfl_down_sync(0xffffffffu, d2, 8);
    d2 += __shfl_down_sync(0xffffffffu, d2, 16);
    if ((tid & 31) == 0) atomicAdd(&sAcc, d2);
    __syncthreads();
    if (tid == 0) d_partialM[blockIdx.x] = sAcc;
}

// ---------------- finalize loss -------------------------------------------
__global__ void fin_k(float* __restrict__ out, int N, int E, int out_size, int nb_m) {
    __shared__ double sS[32];
    __shared__ double red[32];
    int tid = threadIdx.x, w = tid >> 5, lane = tid & 31;

    if (w < NCLS) {
        float s = 0.f;
        for (int k = lane; k < G2MAX; k += 32) s += d_partialS[w * G2MAX + k];
#pragma unroll
        for (int o = 16; o; o >>= 1) s += __shfl_down_sync(0xffffffffu, s, o);
        if (lane == 0) sS[w] = (double)s;
    }

    double m = 0.0;
    for (int k = tid; k < nb_m; k += 1024) m += (double)d_partialM[k];
#pragma unroll
    for (int o = 16; o; o >>= 1) m += __shfl_down_sync(0xffffffffu, m, o);
    if (lane == 0) red[w] = m;
    __syncthreads();

    if (tid == 0) {
        double mm = 0.0;
        for (int i = 0; i < 32; i++) mm += red[i];
        double preg = 0.0;
        for (int c = 0; c < NCLS; c++)
            preg -= log(1.0001 - exp(sS[c]));
        double loss = mm / (double)E + REG_C * preg;
        if (out_size > N * NCLS) out[(size_t)N * NCLS] = (float)loss;
    }
}

// ---------------- launch ---------------------------------------------------
extern "C" void kernel_launch(void* const* d_in, const int* in_sizes, int n_in,
                              void* d_out, int out_size) {
    const float* x   = (const float*)d_in[0];
    const void*  ei  = d_in[1];
    const float* ep  = (const float*)d_in[2];
    const float* W1  = (const float*)d_in[3];
    const float* b1  = (const float*)d_in[4];
    const float* W2  = (const float*)d_in[5];
    const float* b2  = (const float*)d_in[6];
    float* out = (float*)d_out;

    int N = in_sizes[0] / IN_DIM;    // 100000
    int E = in_sizes[2];             // 3200000
    int nb_scan = (N + 1 + 1023) / 1024;
    long long ff_threads = ((long long)E + 1) / 2 * 4;
    int nb_ff   = (int)((ff_threads + 1023) / 1024);
    int n4 = N * CP / 4;

    static cudaStream_t s_aux = nullptr;
    static cudaEvent_t ev_root = nullptr, ev_scan1 = nullptr, ev_g1 = nullptr;
    if (s_aux == nullptr) {
        cudaStreamCreateWithFlags(&s_aux, cudaStreamNonBlocking);
        cudaEventCreateWithFlags(&ev_root, cudaEventDisableTiming);
        cudaEventCreateWithFlags(&ev_scan1, cudaEventDisableTiming);
        cudaEventCreateWithFlags(&ev_g1,   cudaEventDisableTiming);
    }

    const int T = 256;

    // fork: aux stream runs gemm1_raw concurrently with CSR build
    cudaEventRecord(ev_root, 0);
    cudaStreamWaitEvent(s_aux, ev_root, 0);
    gemm1_raw<<<(N + 127) / 128, 128, 0, s_aux>>>(x, W1, N);

    // main chain: CSR build
    init_k       <<<(N + 1 + T - 1) / T, T>>>((const unsigned int*)ei, N);
    count_convert<<<(E + T - 1) / T, T>>>(ei, E);
    scan1        <<<nb_scan, 1024>>>(N);
    cudaEventRecord(ev_scan1, 0);

    cudaStreamWaitEvent(s_aux, ev_scan1, 0);
    scaleg1<<<(n4 + T - 1) / T, T, 0, s_aux>>>(N);
    cudaEventRecord(ev_g1, s_aux);

    scan3        <<<nb_scan, 1024>>>(N);
    fill_k       <<<(E + T - 1) / T, T>>>(E);

    cudaStreamWaitEvent(0, ev_g1, 0);
    gather1      <<<2048, 256>>>(b1, W2, N);
    gather2      <<<G2MAX, 256>>>(b2, out, N);
    ff_k         <<<nb_ff, 1024>>>(ep, E);
    fin_k        <<<1, 1024>>>(out, N, E, out_size, nb_ff);
}

// round 16
// speedup vs baseline: 1.2153x; 1.0132x over previous
#include <cuda_runtime.h>
#include <cuda_bf16.h>
#include <cuda_fp16.h>
#include <cstdint>
#include <math.h>

#define IN_DIM 128
#define HID    32
#define NCLS   30
#define CP     32            // logical row width (features)
#define NMAX   100000
#define EMAX   3200000
#define EPAD   4001024       // >= EMAX + 8*(NMAX+1) + 8
#define G2MAX  2048          // gather2 grid size (fixed)
#define PARTM  32768
#define REG_C  0.01

// ---------------- static scratch ----------------
__device__ float   d_g1 [NMAX * CP];          // raw gemm1 output (fp32 staging)
__device__ __half2 d_g1h[(NMAX + 1) * 16];    // g1*dinv rows, fp16 (64B) + zero row N
__device__ __half2 d_g2h[(NMAX + 1) * 16];    // g2 rows, fp16 (64B) + zero row N
__device__ __nv_bfloat162 d_fx16[NMAX * 16];
__device__ int    d_cnt [NMAX + 1];
__device__ int    d_cur [NMAX + 1];
__device__ int    d_rp  [NMAX + 1];           // padded CSR row pointers (mult of 8)
__device__ int    d_src32[EMAX];
__device__ int    d_dst32[EMAX];
__device__ int    d_csr [EPAD];
__device__ float  d_dinv[NMAX];
__device__ int    d_blocksum[1024];
__device__ float  d_partialS[32 * G2MAX];
__device__ float  d_partialM[PARTM];
__device__ int    d_is64;

// ---------------- init: cnt=0, dtype detect --------------------------------
__global__ void init_k(const unsigned int* __restrict__ w, int N) {
    int i = blockIdx.x * blockDim.x + threadIdx.x;
    if (i <= N) d_cnt[i] = 0;
    if (blockIdx.x == 0 && threadIdx.x < 64) {
        unsigned int v = w[2 * threadIdx.x + 1];
        unsigned int any = __ballot_sync(0xffffffffu, v != 0);
        if (threadIdx.x == 0) d_is64 = (any == 0) ? 1 : 0;
    }
}

// ---------------- count + int32 conversion --------------------------------
__global__ void count_convert(const void* __restrict__ ei, int E) {
    int e = blockIdx.x * blockDim.x + threadIdx.x;
    if (e >= E) return;
    int s, d;
    if (d_is64) {
        const long long* p = (const long long*)ei;
        s = (int)p[e]; d = (int)p[(size_t)E + e];
    } else {
        const int* p = (const int*)ei;
        s = p[e]; d = p[(size_t)E + e];
    }
    d_src32[e] = s; d_dst32[e] = d;
    atomicAdd(&d_cnt[d], 1);
}

// ---------------- scan over PADDED counts (N+1 elements) + fused dinv ------
__global__ void scan1(int N) {
    __shared__ int sh[1024];
    int gid = blockIdx.x * 1024 + threadIdx.x;
    int cnt = 0, v = 0;
    if (gid <= N) { cnt = d_cnt[gid]; v = (cnt + 7) & ~7; }
    if (gid < N) d_dinv[gid] = rsqrtf((float)(cnt + 1));    // +1 self loop
    sh[threadIdx.x] = v; __syncthreads();
    for (int off = 1; off < 1024; off <<= 1) {
        int t = (threadIdx.x >= off) ? sh[threadIdx.x - off] : 0;
        __syncthreads();
        sh[threadIdx.x] += t;
        __syncthreads();
    }
    int incl = sh[threadIdx.x];
    if (gid <= N) d_cur[gid] = incl - v;          // block-local exclusive
    if (threadIdx.x == 1023) d_blocksum[blockIdx.x] = incl;
}

// scan3: inlined block offsets + rp/cursor write + sentinel tail padding
__global__ void scan3(int N) {
    __shared__ int off_sh;
    int lane = threadIdx.x & 31;
    if (threadIdx.x < 32) {
        int s = 0;
        for (int k = lane; k < blockIdx.x; k += 32) s += d_blocksum[k];
#pragma unroll
        for (int o = 16; o; o >>= 1) s += __shfl_down_sync(0xffffffffu, s, o);
        if (lane == 0) off_sh = s;
    }
    __syncthreads();
    int gid = blockIdx.x * 1024 + threadIdx.x;
    if (gid <= N) {
        int rp = d_cur[gid] + off_sh;
        d_rp[gid] = rp;
        d_cur[gid] = rp;                           // fill cursor
        if (gid < N) {
            int c = d_cnt[gid];
            int end = rp + ((c + 7) & ~7);
            for (int p = rp + c; p < end; p++) d_csr[p] = N;   // sentinel tail
        } else {
            for (int p = rp; p < rp + 8; p++) d_csr[p] = N;    // global tail
        }
    }
}

// ---------------- CSR fill -------------------------------------------------
__global__ void fill_k(int E) {
    int e = blockIdx.x * blockDim.x + threadIdx.x;
    if (e >= E) return;
    int d = d_dst32[e];
    int pos = atomicAdd(&d_cur[d], 1);
    d_csr[pos] = d_src32[e];
}

// ---------------- GEMM1 (raw): g1 = x @ W1 (aux stream) --------------------
__global__ void gemm1_raw(const float* __restrict__ x, const float* __restrict__ W1, int N) {
    __shared__ float Ws[IN_DIM * HID];
    for (int i = threadIdx.x; i < IN_DIM * HID; i += blockDim.x) Ws[i] = W1[i];
    __syncthreads();
    int r = blockIdx.x * blockDim.x + threadIdx.x;
    if (r >= N) return;

    float acc[HID];
#pragma unroll
    for (int c = 0; c < HID; c++) acc[c] = 0.f;

    const float4* x4 = reinterpret_cast<const float4*>(x + (size_t)r * IN_DIM);
#pragma unroll 4
    for (int k4 = 0; k4 < IN_DIM / 4; k4++) {
        float4 xv = x4[k4];
        int k = k4 * 4;
#pragma unroll
        for (int c = 0; c < HID; c++) {
            acc[c] += xv.x * Ws[(k + 0) * HID + c]
                    + xv.y * Ws[(k + 1) * HID + c]
                    + xv.z * Ws[(k + 2) * HID + c]
                    + xv.w * Ws[(k + 3) * HID + c];
        }
    }
    float* out = d_g1 + (size_t)r * CP;
#pragma unroll
    for (int c = 0; c < HID; c++) out[c] = acc[c];
}

// -------- scale g1 by dinv and convert to fp16 rows (join point) -----------
__global__ void scaleg1(int N) {
    int i = blockIdx.x * blockDim.x + threadIdx.x;   // one float4 each
    int n4 = N * CP / 4;
    if (i >= n4) return;
    float s = d_dinv[i >> 3];
    float4 v = reinterpret_cast<const float4*>(d_g1)[i];
    __half2 a = __floats2half2_rn(v.x * s, v.y * s);
    __half2 b = __floats2half2_rn(v.z * s, v.w * s);
    d_g1h[2 * i]     = a;     // index = node*16 + quad*2
    d_g1h[2 * i + 1] = b;
}

// ---- gather layer1: fp16 rows, scalar-pair indices, fused GEMM2 -----------
__global__ void __launch_bounds__(256) gather1(const float* __restrict__ b1,
                                               const float* __restrict__ W2, int N) {
    __shared__ float Ws[HID * CP];
    for (int i = threadIdx.x; i < HID * CP; i += blockDim.x) {
        int k = i / CP, c = i % CP;
        Ws[i] = (c < NCLS) ? W2[k * NCLS + c] : 0.f;
    }
    __syncthreads();

    int tid  = threadIdx.x;
    int lane = tid & 31;
    int q    = lane & 7;          // feature quad 0..7
    int eg   = lane >> 3;         // edge group 0..3
    int warp = (blockIdx.x * blockDim.x + tid) >> 5;
    int nwarps = (gridDim.x * blockDim.x) >> 5;
    float4 bv4 = reinterpret_cast<const float4*>(b1)[q];
    const uint2* G1 = reinterpret_cast<const uint2*>(d_g1h);

    for (int v = warp; v < N; v += nwarps) {
        int beg = d_rp[v];
        int nb  = (d_rp[v + 1] - beg) >> 3;          // blocks of 8 edges
        const int2* ip = reinterpret_cast<const int2*>(d_csr + beg) + eg;
        float4 acc = make_float4(0.f, 0.f, 0.f, 0.f);
        int2 cur = ip[0];                            // safe: tail-padded
        for (int b = 0; b < nb; b++) {
            int2 nxt = ip[(b + 1) * 4];              // unconditional prefetch
            uint2 ra = G1[(size_t)cur.x * 8 + q];
            uint2 rb = G1[(size_t)cur.y * 8 + q];
            float2 a0 = __half22float2(*reinterpret_cast<const __half2*>(&ra.x));
            float2 a1 = __half22float2(*reinterpret_cast<const __half2*>(&ra.y));
            float2 b0 = __half22float2(*reinterpret_cast<const __half2*>(&rb.x));
            float2 b1v = __half22float2(*reinterpret_cast<const __half2*>(&rb.y));
            acc.x += a0.x + b0.x;  acc.y += a0.y + b0.y;
            acc.z += a1.x + b1v.x; acc.w += a1.y + b1v.y;
            cur = nxt;
        }
        // reduce across the 4 edge groups
#pragma unroll
        for (int o = 8; o <= 16; o <<= 1) {
            acc.x += __shfl_xor_sync(0xffffffffu, acc.x, o);
            acc.y += __shfl_xor_sync(0xffffffffu, acc.y, o);
            acc.z += __shfl_xor_sync(0xffffffffu, acc.z, o);
            acc.w += __shfl_xor_sync(0xffffffffu, acc.w, o);
        }
        uint2 rs = G1[(size_t)v * 8 + q];
        float2 s0 = __half22float2(*reinterpret_cast<const __half2*>(&rs.x));
        float2 s1 = __half22float2(*reinterpret_cast<const __half2*>(&rs.y));
        float dv = d_dinv[v];
        float4 h;
        h.x = fmaxf(dv * (acc.x + s0.x) + bv4.x, 0.f);
        h.y = fmaxf(dv * (acc.y + s0.y) + bv4.y, 0.f);
        h.z = fmaxf(dv * (acc.z + s1.x) + bv4.z, 0.f);
        h.w = fmaxf(dv * (acc.w + s1.y) + bv4.w, 0.f);

        // fused GEMM2: g2[c] = dv * sum_k h[k] * W2[k][c], c = lane
        float g2c = 0.f;
#pragma unroll
        for (int q2 = 0; q2 < 8; q2++) {
            float hx = __shfl_sync(0xffffffffu, h.x, q2);
            float hy = __shfl_sync(0xffffffffu, h.y, q2);
            float hz = __shfl_sync(0xffffffffu, h.z, q2);
            float hw = __shfl_sync(0xffffffffu, h.w, q2);
            g2c += hx * Ws[(4 * q2 + 0) * CP + lane] + hy * Ws[(4 * q2 + 1) * CP + lane]
                 + hz * Ws[(4 * q2 + 2) * CP + lane] + hw * Ws[(4 * q2 + 3) * CP + lane];
        }
        float val = dv * g2c;
        // pack pairs of lanes into half2 and store fp16 row
        float partner = __shfl_down_sync(0xffffffffu, val, 1);
        if ((lane & 1) == 0)
            d_g2h[(size_t)v * 16 + (lane >> 1)] = __floats2half2_rn(val, partner);
    }
}

// ---- gather layer2: fp16 rows + softmax + FX + bf16 copy + NFX ------------
__global__ void __launch_bounds__(256) gather2(const float* __restrict__ b2,
                                               float* __restrict__ fx_out, int N) {
    __shared__ float Ss[32];
    __shared__ float b2s[32];
    int tid  = threadIdx.x;
    int lane = tid & 31;
    if (tid < 32) { Ss[tid] = 0.f; b2s[tid] = (tid < NCLS) ? b2[tid] : 0.f; }
    __syncthreads();

    int q    = lane & 7;
    int eg   = lane >> 3;
    int warp = (blockIdx.x * blockDim.x + tid) >> 5;
    int nwarps = (gridDim.x * blockDim.x) >> 5;
    float4 bv4 = reinterpret_cast<const float4*>(b2s)[q];
    float4 ls4 = make_float4(0.f, 0.f, 0.f, 0.f);
    const uint2* G2 = reinterpret_cast<const uint2*>(d_g2h);

    for (int v = warp; v < N; v += nwarps) {
        int beg = d_rp[v];
        int nb  = (d_rp[v + 1] - beg) >> 3;
        const int2* ip = reinterpret_cast<const int2*>(d_csr + beg) + eg;
        float4 acc = make_float4(0.f, 0.f, 0.f, 0.f);
        int2 cur = ip[0];
        for (int b = 0; b < nb; b++) {
            int2 nxt = ip[(b + 1) * 4];
            uint2 ra = G2[(size_t)cur.x * 8 + q];
            uint2 rb = G2[(size_t)cur.y * 8 + q];
            float2 a0 = __half22float2(*reinterpret_cast<const __half2*>(&ra.x));
            float2 a1 = __half22float2(*reinterpret_cast<const __half2*>(&ra.y));
            float2 b0 = __half22float2(*reinterpret_cast<const __half2*>(&rb.x));
            float2 b1v = __half22float2(*reinterpret_cast<const __half2*>(&rb.y));
            acc.x += a0.x + b0.x;  acc.y += a0.y + b0.y;
            acc.z += a1.x + b1v.x; acc.w += a1.y + b1v.y;
            cur = nxt;
        }
#pragma unroll
        for (int o = 8; o <= 16; o <<= 1) {
            acc.x += __shfl_xor_sync(0xffffffffu, acc.x, o);
            acc.y += __shfl_xor_sync(0xffffffffu, acc.y, o);
            acc.z += __shfl_xor_sync(0xffffffffu, acc.z, o);
            acc.w += __shfl_xor_sync(0xffffffffu, acc.w, o);
        }
        uint2 rs = G2[(size_t)v * 8 + q];
        float2 s0 = __half22float2(*reinterpret_cast<const __half2*>(&rs.x));
        float2 s1 = __half22float2(*reinterpret_cast<const __half2*>(&rs.y));
        float dv = d_dinv[v];
        float4 lg;
        lg.x = dv * (acc.x + s0.x) + bv4.x;
        lg.y = dv * (acc.y + s0.y) + bv4.y;
        lg.z = dv * (acc.z + s1.x) + bv4.z;
        lg.w = dv * (acc.w + s1.y) + bv4.w;
        if (q == 7) { lg.z = -1e30f; lg.w = -1e30f; }   // classes 30,31

        float mx = fmaxf(fmaxf(lg.x, lg.y), fmaxf(lg.z, lg.w));
#pragma unroll
        for (int o = 1; o <= 4; o <<= 1) mx = fmaxf(mx, __shfl_xor_sync(0xffffffffu, mx, o));
        float4 ex;
        ex.x = expf(lg.x - mx); ex.y = expf(lg.y - mx);
        ex.z = expf(lg.z - mx); ex.w = expf(lg.w - mx);
        float sum = ex.x + ex.y + ex.z + ex.w;
#pragma unroll
        for (int o = 1; o <= 4; o <<= 1) sum += __shfl_xor_sync(0xffffffffu, sum, o);
        float inv = 1.f / sum;
        float4 fx;
        fx.x = ex.x * inv; fx.y = ex.y * inv; fx.z = ex.z * inv; fx.w = ex.w * inv;

        if (eg == 0) {
            float* base = fx_out + (size_t)v * NCLS;
            *reinterpret_cast<float2*>(base + 4 * q) = make_float2(fx.x, fx.y);
            if (q < 7)
                *reinterpret_cast<float2*>(base + 4 * q + 2) = make_float2(fx.z, fx.w);
            __nv_bfloat162 p0 = __floats2bfloat162_rn(fx.x, fx.y);
            __nv_bfloat162 p1 = __floats2bfloat162_rn(fx.z, fx.w);
            d_fx16[(size_t)v * 16 + 2 * q]     = p0;
            d_fx16[(size_t)v * 16 + 2 * q + 1] = p1;
        }
        ls4.x += log1pf(-fx.x * fx.x);
        ls4.y += log1pf(-fx.y * fx.y);
        ls4.z += log1pf(-fx.z * fx.z);
        ls4.w += log1pf(-fx.w * fx.w);
    }
    if (eg == 0) {
        atomicAdd(&Ss[4 * q + 0], ls4.x);
        atomicAdd(&Ss[4 * q + 1], ls4.y);
        atomicAdd(&Ss[4 * q + 2], ls4.z);
        atomicAdd(&Ss[4 * q + 3], ls4.w);
    }
    __syncthreads();
    if (tid < NCLS) d_partialS[tid * gridDim.x + blockIdx.x] = Ss[tid];
}

// ---------------- FF + MSE partials (2 edges per 4-lane group) -------------
__global__ void ff_k(const float* __restrict__ ep, int E) {
    __shared__ float sAcc;
    int tid = threadIdx.x;
    if (tid == 0) sAcc = 0.f;
    __syncthreads();

    int idx = blockIdx.x * blockDim.x + tid;
    int grp = idx >> 2, c = idx & 3;
    int e0 = grp * 2;
    int nGrp = (E + 1) >> 1;
    bool v0 = (grp < nGrp) && (e0 < E);
    bool v1 = (grp < nGrp) && (e0 + 1 < E);

    float p0 = 0.f, p1 = 0.f;
    if (v0) {
        int s0 = d_src32[e0], dd0 = d_dst32[e0];
        uint4 A0 = reinterpret_cast<const uint4*>(d_fx16 + (size_t)s0  * 16)[c];
        uint4 B0 = reinterpret_cast<const uint4*>(d_fx16 + (size_t)dd0 * 16)[c];
        const unsigned int aw[4] = {A0.x, A0.y, A0.z, A0.w};
        const unsigned int bw[4] = {B0.x, B0.y, B0.z, B0.w};
#pragma unroll
        for (int j = 0; j < 4; j++) {
            float2 af = __bfloat1622float2(*reinterpret_cast<const __nv_bfloat162*>(&aw[j]));
            float2 bf = __bfloat1622float2(*reinterpret_cast<const __nv_bfloat162*>(&bw[j]));
            p0 += af.x * bf.x + af.y * bf.y;
        }
    }
    if (v1) {
        int s1 = d_src32[e0 + 1], dd1 = d_dst32[e0 + 1];
        uint4 A1 = reinterpret_cast<const uint4*>(d_fx16 + (size_t)s1  * 16)[c];
        uint4 B1 = reinterpret_cast<const uint4*>(d_fx16 + (size_t)dd1 * 16)[c];
        const unsigned int aw[4] = {A1.x, A1.y, A1.z, A1.w};
        const unsigned int bw[4] = {B1.x, B1.y, B1.z, B1.w};
#pragma unroll
        for (int j = 0; j < 4; j++) {
            float2 af = __bfloat1622float2(*reinterpret_cast<const __nv_bfloat162*>(&aw[j]));
            float2 bf = __bfloat1622float2(*reinterpret_cast<const __nv_bfloat162*>(&bw[j]));
            p1 += af.x * bf.x + af.y * bf.y;
        }
    }

    p0 += __shfl_down_sync(0xffffffffu, p0, 1);
    p0 += __shfl_down_sync(0xffffffffu, p0, 2);
    p1 += __shfl_down_sync(0xffffffffu, p1, 1);
    p1 += __shfl_down_sync(0xffffffffu, p1, 2);

    float d2 = 0.f;
    if (c == 0) {
        if (v0) { float f = p0 - ep[e0];     d2 += f * f; }
        if (v1) { float f = p1 - ep[e0 + 1]; d2 += f * f; }
    }
    d2 += __shfl_down_sync(0xffffffffu, d2, 4);
    d2 += __shfl_down_sync(0xffffffffu, d2, 8);
    d2 += __shfl_down_sync(0xffffffffu, d2, 16);
    if ((tid & 31) == 0) atomicAdd(&sAcc, d2);
    __syncthreads();
    if (tid == 0) d_partialM[blockIdx.x] = sAcc;
}

// ---------------- finalize loss -------------------------------------------
__global__ void fin_k(float* __restrict__ out, int N, int E, int out_size, int nb_m) {
    __shared__ double sS[32];
    __shared__ double red[32];
    int tid = threadIdx.x, w = tid >> 5, lane = tid & 31;

    if (w < NCLS) {
        float s = 0.f;
        for (int k = lane; k < G2MAX; k += 32) s += d_partialS[w * G2MAX + k];
#pragma unroll
        for (int o = 16; o; o >>= 1) s += __shfl_down_sync(0xffffffffu, s, o);
        if (lane == 0) sS[w] = (double)s;
    }

    double m = 0.0;
    for (int k = tid; k < nb_m; k += 1024) m += (double)d_partialM[k];
#pragma unroll
    for (int o = 16; o; o >>= 1) m += __shfl_down_sync(0xffffffffu, m, o);
    if (lane == 0) red[w] = m;
    __syncthreads();

    if (tid == 0) {
        double mm = 0.0;
        for (int i = 0; i < 32; i++) mm += red[i];
        double preg = 0.0;
        for (int c = 0; c < NCLS; c++)
            preg -= log(1.0001 - exp(sS[c]));
        double loss = mm / (double)E + REG_C * preg;
        if (out_size > N * NCLS) out[(size_t)N * NCLS] = (float)loss;
    }
}

// ---------------- launch ---------------------------------------------------
extern "C" void kernel_launch(void* const* d_in, const int* in_sizes, int n_in,
                              void* d_out, int out_size) {
    const float* x   = (const float*)d_in[0];
    const void*  ei  = d_in[1];
    const float* ep  = (const float*)d_in[2];
    const float* W1  = (const float*)d_in[3];
    const float* b1  = (const float*)d_in[4];
    const float* W2  = (const float*)d_in[5];
    const float* b2  = (const float*)d_in[6];
    float* out = (float*)d_out;

    int N = in_sizes[0] / IN_DIM;    // 100000
    int E = in_sizes[2];             // 3200000
    int nb_scan = (N + 1 + 1023) / 1024;
    long long ff_threads = ((long long)E + 1) / 2 * 4;
    int nb_ff   = (int)((ff_threads + 1023) / 1024);
    int n4 = N * CP / 4;

    static cudaStream_t s_aux = nullptr;
    static cudaEvent_t ev_root = nullptr, ev_scan1 = nullptr, ev_g1 = nullptr;
    if (s_aux == nullptr) {
        cudaStreamCreateWithFlags(&s_aux, cudaStreamNonBlocking);
        cudaEventCreateWithFlags(&ev_root, cudaEventDisableTiming);
        cudaEventCreateWithFlags(&ev_scan1, cudaEventDisableTiming);
        cudaEventCreateWithFlags(&ev_g1,   cudaEventDisableTiming);
    }

    const int T = 256;

    // fork: aux stream runs gemm1_raw concurrently with CSR build
    cudaEventRecord(ev_root, 0);
    cudaStreamWaitEvent(s_aux, ev_root, 0);
    gemm1_raw<<<(N + 127) / 128, 128, 0, s_aux>>>(x, W1, N);

    // main chain: CSR build
    init_k       <<<(N + 1 + T - 1) / T, T>>>((const unsigned int*)ei, N);
    count_convert<<<(E + T - 1) / T, T>>>(ei, E);
    scan1        <<<nb_scan, 1024>>>(N);
    cudaEventRecord(ev_scan1, 0);

    cudaStreamWaitEvent(s_aux, ev_scan1, 0);
    scaleg1<<<(n4 + T - 1) / T, T, 0, s_aux>>>(N);
    cudaEventRecord(ev_g1, s_aux);

    scan3        <<<nb_scan, 1024>>>(N);
    fill_k       <<<(E + T - 1) / T, T>>>(E);

    cudaStreamWaitEvent(0, ev_g1, 0);
    gather1      <<<2048, 256>>>(b1, W2, N);
    gather2      <<<G2MAX, 256>>>(b2, out, N);
    ff_k         <<<nb_ff, 1024>>>(ep, E);
    fin_k        <<<1, 1024>>>(out, N, E, out_size, nb_ff);
}